// round 9
// baseline (speedup 1.0000x reference)
#include <cuda_runtime.h>
#include <cstdint>

// Fuzzy LeNet-5, Yager p=1 == Lukasiewicz: conv_out = relu(max(x+w) - 1);
// relu/maxpool fold into one max over (2x2 pool)x(5x5 field).
// Convs in s16 fixed point (scale 16383) with DPX __viaddmax_s16x2 (1 instr =
// 2 max-plus terms; the two conv rows of a pooled cell live in the s16 lanes).
// R9: L1 job order permuted to ph-major so a warp's lanes share x rows
// (LDS broadcast windows: 1 wavefront per x-load instead of ~6), w1 repacked
// [c*5+kh][o][8] so the warp's weight rows sit in 192 contiguous bytes.

#define NT 640
#define SCALE 16383.0f
#define ISCALE (1.0f / 16383.0f)
#define IONE 16383

__device__ __forceinline__ unsigned smem_u32(const void* p) {
    return (unsigned)__cvta_generic_to_shared(p);
}
__device__ __forceinline__ void cp4(float* dst, const float* src) {
    asm volatile("cp.async.ca.shared.global [%0], [%1], 4;\n"
                 :: "r"(smem_u32(dst)), "l"(src));
}

// One weight row (5 taps) against 8 packed pair-columns -> updates 4 chains:
// A0/A1 = output pw (cols 0..5), B0/B1 = output pw+1 (cols 2..7).
__device__ __forceinline__ void taps_pair(uint32_t& A0, uint32_t& A1,
                                          uint32_t& B0, uint32_t& B1,
                                          const uint32_t* __restrict__ row,
                                          const uint32_t* __restrict__ wr)
{
    const uint4 Xa = *reinterpret_cast<const uint4*>(row);      // cols 0..3
    const uint4 Xb = *reinterpret_cast<const uint4*>(row + 4);  // cols 4..7
    const uint4 W  = *reinterpret_cast<const uint4*>(wr);       // w0..w3
    const uint32_t w4 = wr[4];
    A0 = __viaddmax_s16x2(Xa.x, W.x, A0);
    A1 = __viaddmax_s16x2(Xa.y, W.x, A1);
    B0 = __viaddmax_s16x2(Xa.z, W.x, B0);
    B1 = __viaddmax_s16x2(Xa.w, W.x, B1);
    A0 = __viaddmax_s16x2(Xa.y, W.y, A0);
    A1 = __viaddmax_s16x2(Xa.z, W.y, A1);
    B0 = __viaddmax_s16x2(Xa.w, W.y, B0);
    B1 = __viaddmax_s16x2(Xb.x, W.y, B1);
    A0 = __viaddmax_s16x2(Xa.z, W.z, A0);
    A1 = __viaddmax_s16x2(Xa.w, W.z, A1);
    B0 = __viaddmax_s16x2(Xb.x, W.z, B0);
    B1 = __viaddmax_s16x2(Xb.y, W.z, B1);
    A0 = __viaddmax_s16x2(Xa.w, W.w, A0);
    A1 = __viaddmax_s16x2(Xb.x, W.w, A1);
    B0 = __viaddmax_s16x2(Xb.y, W.w, B0);
    B1 = __viaddmax_s16x2(Xb.z, W.w, B1);
    A0 = __viaddmax_s16x2(Xb.x, w4, A0);
    A1 = __viaddmax_s16x2(Xb.y, w4, A1);
    B0 = __viaddmax_s16x2(Xb.z, w4, B0);
    B1 = __viaddmax_s16x2(Xb.w, w4, B1);
}

// Pooled max-plus pair of cells. x: packed pair-rows at base (2ph, 4pwp),
// 16B-aligned. w: weight base; block (c,kh) at w + (c*5+kh)*WSTRIDE.
template<int NC, int CSTRIDE, int PITCH, int WSTRIDE>
__device__ __forceinline__ void mp_pair(const uint32_t* __restrict__ x,
                                        const uint32_t* __restrict__ w,
                                        int& m0, int& m1)
{
    uint32_t A0 = 0u, A1 = 0u, B0 = 0u, B1 = 0u;
    #pragma unroll
    for (int c = 0; c < NC; ++c) {
        #pragma unroll
        for (int kh = 0; kh < 5; ++kh)
            taps_pair(A0, A1, B0, B1,
                      x + c * CSTRIDE + kh * PITCH, w + (c * 5 + kh) * WSTRIDE);
    }
    const uint32_t ca = __viaddmax_s16x2(A0, 0u, A1);
    const uint32_t cb = __viaddmax_s16x2(B0, 0u, B1);
    m0 = max((int)(ca & 0xFFFFu), (int)(ca >> 16));   // values <= 32766
    m1 = max((int)(cb & 0xFFFFu), (int)(cb >> 16));
}

// dynamic smem layout (32-bit words)
#define OFF_IN   0       // 3072 f
#define OFF_W1R  3072    // 720 u32: [c*5+kh][o:6][8] padded (w,w)
#define OFF_P1   3808    // 2976 u32: [3][31][32] input pair-rows (rows 128B-aligned)
#define OFF_P2   6784    // 1248 u32: [6][13][16] L1-out pair-rows (padded)
#define OFF_W2P  8032    // 3840 u32: [16][6][5][8]
#define OFF_L2F  11872   // 400 f (16B aligned)
#define OFF_L3   12272   // 120 f
#define OFF_H    12392   // 84 f
#define OFF_WD   12476   // 10080 f
#define OFF_WF   22556   // 840 f
#define OFF_BF   23396   // 10 f
#define SMEM_WORDS 23406

__global__ __launch_bounds__(NT, 1)
void lenet_fuzzy_kernel(const float* __restrict__ g_in,
                        const float* __restrict__ g_w1,
                        const float* __restrict__ g_w2,
                        const float* __restrict__ g_w3,
                        const float* __restrict__ g_wd,
                        const float* __restrict__ g_wf,
                        const float* __restrict__ g_bf,
                        float* __restrict__ g_out)
{
    extern __shared__ uint32_t sm[];
    float*    s_in  = reinterpret_cast<float*>(sm + OFF_IN);
    uint32_t* s_w1r = sm + OFF_W1R;
    uint32_t* s_p1  = sm + OFF_P1;
    uint32_t* s_p2  = sm + OFF_P2;
    uint32_t* s_w2p = sm + OFF_W2P;
    float*    s_l2f = reinterpret_cast<float*>(sm + OFF_L2F);
    float*    s_l3  = reinterpret_cast<float*>(sm + OFF_L3);
    float*    s_h   = reinterpret_cast<float*>(sm + OFF_H);
    float*    s_wd  = reinterpret_cast<float*>(sm + OFF_WD);
    float*    s_wf  = reinterpret_cast<float*>(sm + OFF_WF);
    float*    s_bf  = reinterpret_cast<float*>(sm + OFF_BF);

    const int b    = blockIdx.x;
    const int tid  = threadIdx.x;
    const int warp = tid >> 5;
    const int lane = tid & 31;

    // ---- async staging of head weights (consumed after L3) ----
    for (int i = tid; i < 10080; i += NT) cp4(s_wd + i, g_wd + i);
    for (int i = tid; i < 840;   i += NT) cp4(s_wf + i, g_wf + i);
    if (tid < 10) cp4(s_bf + tid, g_bf + tid);
    asm volatile("cp.async.commit_group;\n");

    // ---- stage image; quantize+pack conv weights; zero P2 pad columns ----
    {
        const float4* img4 = reinterpret_cast<const float4*>(g_in + (size_t)b * 3072);
        float4* sin4 = reinterpret_cast<float4*>(s_in);
        #pragma unroll
        for (int i = tid; i < 768; i += NT) sin4[i] = img4[i];
        // w1 [o][c][kh][kw] -> s_w1r[(c*5+kh)*48 + o*8 + kw]
        for (int i = tid; i < 450; i += NT) {
            const int o = i / 75, r = i - o * 75;      // r = c*25 + kh*5 + kw
            const int rk = r / 5, kw = r - rk * 5;     // rk = c*5 + kh
            const int v = __float2int_rn(g_w1[i] * SCALE);
            s_w1r[rk * 48 + o * 8 + kw] = (uint32_t)(v | (v << 16));
        }
        // w2 [o][c][kh][kw] -> s_w2p[o*240 + rk*8 + kw]
        for (int i = tid; i < 2400; i += NT) {
            const int o = i / 150, r = i - o * 150;
            const int rk = r / 5, kw = r - rk * 5;
            const int v = __float2int_rn(g_w2[i] * SCALE);
            s_w2p[o * 240 + rk * 8 + kw] = (uint32_t)(v | (v << 16));
        }
        // P2 padding cols 14,15 of each pair-row (read only by discarded chains)
        for (int i = tid; i < 78; i += NT) {
            s_p2[i * 16 + 14] = 0u;
            s_p2[i * 16 + 15] = 0u;
        }
    }
    __syncthreads();

    // ---- quantize input into pair-rows P1[c][i][col] = (row i, row i+1) ----
    for (int idx = tid; idx < 2976; idx += NT) {
        const int c   = idx / 992;           // 31*32
        const int rem = idx - c * 992;
        const float* p = s_in + c * 1024 + rem;
        const int v0 = __float2int_rn(p[0]  * SCALE);
        const int v1 = __float2int_rn(p[32] * SCALE);
        s_p1[idx] = (uint32_t)(v0 | (v1 << 16));
    }
    __syncthreads();

    // ---- Layer 1: (3->6) conv5+relu+pool2, one output-PAIR per thread.
    //      Job order ph-major: warp lanes share the x rows (broadcast windows)
    //      and read 6 adjacent weight rows (192B). ----
    if (tid < 588) {                          // 14 rows * 6 ch * 7 pairs
        const int ph  = tid / 42;             // out row 0..13
        const int rem = tid - ph * 42;
        const int o   = rem / 7;              // out channel 0..5
        const int pwp = rem - o * 7;          // pair 0..6 -> cols 2pwp, 2pwp+1
        int m0, m1;
        mp_pair<3, 992, 32, 48>(s_p1 + (2 * ph) * 32 + 4 * pwp, s_w1r + o * 8, m0, m1);
        const uint16_t v0 = (uint16_t)max(m0 - IONE, 0);
        const uint16_t v1 = (uint16_t)max(m1 - IONE, 0);
        uint16_t* p2h = reinterpret_cast<uint16_t*>(s_p2);
        const int pw0 = 2 * pwp;
        // P2[o][i][col]: lo = L1 row i, hi = L1 row i+1  (i in 0..12, stride 16)
        if (ph <= 12) {
            p2h[2 * (o * 208 + ph * 16 + pw0)]           = v0;
            p2h[2 * (o * 208 + ph * 16 + pw0 + 1)]       = v1;
        }
        if (ph >= 1) {
            p2h[2 * (o * 208 + (ph - 1) * 16 + pw0) + 1]     = v0;
            p2h[2 * (o * 208 + (ph - 1) * 16 + pw0 + 1) + 1] = v1;
        }
    }
    __syncthreads();

    // ---- Layer 2: (6->16) conv5+relu+pool2, 2 threads per output-pair
    //      (3 input channels each), shfl-combined ----
    if (tid < 480) {                          // 16 o * 5 ph * 3 colgroups * 2
        const int half = tid & 1;
        const int pi   = tid >> 1;            // 0..239
        const int o    = pi / 15;
        const int rem  = pi - o * 15;
        const int ph   = rem / 3;             // out row 0..4
        const int cg   = rem - ph * 3;        // colgroup: pw = 2cg, 2cg+1 (cg2: pw 4 only)
        int m0, m1;
        mp_pair<3, 208, 16, 8>(s_p2 + (half * 3) * 208 + (2 * ph) * 16 + 4 * cg,
                               s_w2p + o * 240 + half * 120, m0, m1);
        m0 = max(m0, __shfl_xor_sync(0xffffffffu, m0, 1));
        m1 = max(m1, __shfl_xor_sync(0xffffffffu, m1, 1));
        if (half == 0) {
            const int base = o * 25 + ph * 5 + 2 * cg;
            s_l2f[base] = (float)max(m0 - IONE, 0) * ISCALE;
            if (cg < 2) s_l2f[base + 1] = (float)max(m1 - IONE, 0) * ISCALE;
        }
    }
    __syncthreads();

    // ---- Layer 3: (16->120), 4 threads per output, 25 LDG.128 in flight ----
    if (tid < 480) {
        const int o = tid >> 2;
        const int q = tid & 3;
        const float4* w4 = reinterpret_cast<const float4*>(g_w3 + (size_t)o * 400 + q * 100);
        const float4* x4 = reinterpret_cast<const float4*>(s_l2f) + q * 25;
        float m = 0.f;
        #pragma unroll
        for (int k = 0; k < 25; ++k) {
            const float4 wv = w4[k];
            const float4 xv = x4[k];
            m = fmaxf(m, xv.x + wv.x);
            m = fmaxf(m, xv.y + wv.y);
            m = fmaxf(m, xv.z + wv.z);
            m = fmaxf(m, xv.w + wv.w);
        }
        m = fmaxf(m, __shfl_xor_sync(0xffffffffu, m, 1));
        m = fmaxf(m, __shfl_xor_sync(0xffffffffu, m, 2));
        if (q == 0) s_l3[o] = fmaxf(0.f, m - 1.f);
    }
    asm volatile("cp.async.wait_group 0;\n");
    __syncthreads();

    // ---- DenseDefuzzy: h = tanh(l3 @ wd), 4 threads per output ----
    {
        const int q  = tid & 3;
        const int j  = tid >> 2;
        const int jj = (j < 84) ? j : 83;
        float acc = 0.f;
        const int k0 = q * 30;
        #pragma unroll
        for (int k = 0; k < 30; ++k)
            acc += s_l3[k0 + k] * s_wd[(k0 + k) * 84 + jj];
        acc += __shfl_xor_sync(0xffffffffu, acc, 1);
        acc += __shfl_xor_sync(0xffffffffu, acc, 2);
        if (q == 0 && j < 84) s_h[j] = tanhf(acc);
    }
    __syncthreads();

    // ---- fc5 + log_softmax in warp 0 ----
    if (warp == 0) {
        const int l = (lane < 10) ? lane : 9;
        float acc = s_bf[l];
        #pragma unroll
        for (int j = 0; j < 84; ++j)
            acc += s_h[j] * s_wf[j * 10 + l];
        float v = (lane < 10) ? acc : -1e30f;
        #pragma unroll
        for (int s = 16; s; s >>= 1)
            v = fmaxf(v, __shfl_xor_sync(0xffffffffu, v, s));
        float e = (lane < 10) ? expf(acc - v) : 0.f;
        #pragma unroll
        for (int s = 16; s; s >>= 1)
            e += __shfl_xor_sync(0xffffffffu, e, s);
        const float ls = v + logf(e);
        if (lane < 10) g_out[(size_t)b * 10 + lane] = acc - ls;
    }
}

extern "C" void kernel_launch(void* const* d_in, const int* in_sizes, int n_in,
                              void* d_out, int out_size)
{
    const float* inp = (const float*)d_in[0];
    const float* w1  = (const float*)d_in[1];
    const float* w2  = (const float*)d_in[2];
    const float* w3  = (const float*)d_in[3];
    const float* wd  = (const float*)d_in[4];
    const float* wf  = (const float*)d_in[5];
    const float* bf  = (const float*)d_in[6];
    float* out = (float*)d_out;

    const int B = in_sizes[0] / (3 * 32 * 32);
    const int smem_bytes = SMEM_WORDS * 4;
    cudaFuncSetAttribute(lenet_fuzzy_kernel,
                         cudaFuncAttributeMaxDynamicSharedMemorySize, smem_bytes);
    lenet_fuzzy_kernel<<<B, NT, smem_bytes>>>(inp, w1, w2, w3, wd, wf, bf, out);
}

// round 11
// speedup vs baseline: 1.0135x; 1.0135x over previous
#include <cuda_runtime.h>
#include <cstdint>

// Fuzzy LeNet-5, Yager p=1 == Lukasiewicz: conv_out = relu(max(x+w) - 1);
// relu/maxpool fold into one max over (2x2 pool)x(5x5 field).
// Convs in s16 fixed point (scale 16383) with DPX __viaddmax_s16x2 (1 instr =
// 2 max-plus terms; the two conv rows of a pooled cell live in the s16 lanes).
// R10: staging slimmed — 8B cp.async for head weights, input quantized
// directly from global (no float image staging pass).

#define NT 640
#define SCALE 16383.0f
#define ISCALE (1.0f / 16383.0f)
#define IONE 16383

__device__ __forceinline__ unsigned smem_u32(const void* p) {
    return (unsigned)__cvta_generic_to_shared(p);
}
__device__ __forceinline__ void cp8(float* dst, const float* src) {
    asm volatile("cp.async.ca.shared.global [%0], [%1], 8;\n"
                 :: "r"(smem_u32(dst)), "l"(src));
}

// One weight row (5 taps) against 8 packed pair-columns -> updates 4 chains:
// A0/A1 = output pw (cols 0..5), B0/B1 = output pw+1 (cols 2..7).
__device__ __forceinline__ void taps_pair(uint32_t& A0, uint32_t& A1,
                                          uint32_t& B0, uint32_t& B1,
                                          const uint32_t* __restrict__ row,
                                          const uint32_t* __restrict__ wr)
{
    const uint4 Xa = *reinterpret_cast<const uint4*>(row);      // cols 0..3
    const uint4 Xb = *reinterpret_cast<const uint4*>(row + 4);  // cols 4..7
    const uint4 W  = *reinterpret_cast<const uint4*>(wr);       // w0..w3
    const uint32_t w4 = wr[4];
    A0 = __viaddmax_s16x2(Xa.x, W.x, A0);
    A1 = __viaddmax_s16x2(Xa.y, W.x, A1);
    B0 = __viaddmax_s16x2(Xa.z, W.x, B0);
    B1 = __viaddmax_s16x2(Xa.w, W.x, B1);
    A0 = __viaddmax_s16x2(Xa.y, W.y, A0);
    A1 = __viaddmax_s16x2(Xa.z, W.y, A1);
    B0 = __viaddmax_s16x2(Xa.w, W.y, B0);
    B1 = __viaddmax_s16x2(Xb.x, W.y, B1);
    A0 = __viaddmax_s16x2(Xa.z, W.z, A0);
    A1 = __viaddmax_s16x2(Xa.w, W.z, A1);
    B0 = __viaddmax_s16x2(Xb.x, W.z, B0);
    B1 = __viaddmax_s16x2(Xb.y, W.z, B1);
    A0 = __viaddmax_s16x2(Xa.w, W.w, A0);
    A1 = __viaddmax_s16x2(Xb.x, W.w, A1);
    B0 = __viaddmax_s16x2(Xb.y, W.w, B0);
    B1 = __viaddmax_s16x2(Xb.z, W.w, B1);
    A0 = __viaddmax_s16x2(Xb.x, w4, A0);
    A1 = __viaddmax_s16x2(Xb.y, w4, A1);
    B0 = __viaddmax_s16x2(Xb.z, w4, B0);
    B1 = __viaddmax_s16x2(Xb.w, w4, B1);
}

// Pooled max-plus pair of cells. x: packed pair-rows at base (2ph, 4pwp),
// 16B-aligned. w: weight base; block (c,kh) at w + (c*5+kh)*WSTRIDE.
template<int NC, int CSTRIDE, int PITCH, int WSTRIDE>
__device__ __forceinline__ void mp_pair(const uint32_t* __restrict__ x,
                                        const uint32_t* __restrict__ w,
                                        int& m0, int& m1)
{
    uint32_t A0 = 0u, A1 = 0u, B0 = 0u, B1 = 0u;
    #pragma unroll
    for (int c = 0; c < NC; ++c) {
        #pragma unroll
        for (int kh = 0; kh < 5; ++kh)
            taps_pair(A0, A1, B0, B1,
                      x + c * CSTRIDE + kh * PITCH, w + (c * 5 + kh) * WSTRIDE);
    }
    const uint32_t ca = __viaddmax_s16x2(A0, 0u, A1);
    const uint32_t cb = __viaddmax_s16x2(B0, 0u, B1);
    m0 = max((int)(ca & 0xFFFFu), (int)(ca >> 16));   // values <= 32766
    m1 = max((int)(cb & 0xFFFFu), (int)(cb >> 16));
}

// dynamic smem layout (32-bit words)
#define OFF_W1R  0       // 720 u32: [c*5+kh][o:6][8] padded (w,w)
#define OFF_P1   736     // 2976 u32: [3][31][32] input pair-rows (128B rows)
#define OFF_P2   3712    // 1248 u32: [6][13][16] L1-out pair-rows (padded)
#define OFF_W2P  4960    // 3840 u32: [16][6][5][8]
#define OFF_L2F  8800    // 400 f (16B aligned)
#define OFF_L3   9200    // 120 f
#define OFF_H    9320    // 84 f
#define OFF_WD   9404    // 10080 f (8B aligned)
#define OFF_WF   19484   // 840 f
#define OFF_BF   20324   // 10 f
#define SMEM_WORDS 20336

__global__ __launch_bounds__(NT, 1)
void lenet_fuzzy_kernel(const float* __restrict__ g_in,
                        const float* __restrict__ g_w1,
                        const float* __restrict__ g_w2,
                        const float* __restrict__ g_w3,
                        const float* __restrict__ g_wd,
                        const float* __restrict__ g_wf,
                        const float* __restrict__ g_bf,
                        float* __restrict__ g_out)
{
    extern __shared__ uint32_t sm[];
    uint32_t* s_w1r = sm + OFF_W1R;
    uint32_t* s_p1  = sm + OFF_P1;
    uint32_t* s_p2  = sm + OFF_P2;
    uint32_t* s_w2p = sm + OFF_W2P;
    float*    s_l2f = reinterpret_cast<float*>(sm + OFF_L2F);
    float*    s_l3  = reinterpret_cast<float*>(sm + OFF_L3);
    float*    s_h   = reinterpret_cast<float*>(sm + OFF_H);
    float*    s_wd  = reinterpret_cast<float*>(sm + OFF_WD);
    float*    s_wf  = reinterpret_cast<float*>(sm + OFF_WF);
    float*    s_bf  = reinterpret_cast<float*>(sm + OFF_BF);

    const int b    = blockIdx.x;
    const int tid  = threadIdx.x;
    const int warp = tid >> 5;
    const int lane = tid & 31;

    // ---- async staging of head weights, 8B granules (consumed after L3) ----
    for (int i = tid; i < 5040; i += NT) cp8(s_wd + 2 * i, g_wd + 2 * i);
    for (int i = tid; i < 420;  i += NT) cp8(s_wf + 2 * i, g_wf + 2 * i);
    if (tid < 5) cp8(s_bf + 2 * tid, g_bf + 2 * tid);
    asm volatile("cp.async.commit_group;\n");

    // ---- quantize input DIRECTLY from global into pair-rows
    //      P1[c][i][col] = (row i, row i+1); job = (c, pair-row i, 8-col group)
    if (tid < 372) {                          // 3 ch * 31 rows * 4 groups
        const int c   = tid / 124;
        const int rem = tid - c * 124;
        const int pr  = rem >> 2;             // pair row 0..30
        const int q   = rem & 3;              // col group: cols 8q..8q+7
        const float* gp = g_in + (size_t)b * 3072 + c * 1024 + pr * 32 + 8 * q;
        const float4 a0 = *reinterpret_cast<const float4*>(gp);
        const float4 a1 = *reinterpret_cast<const float4*>(gp + 4);
        const float4 b0 = *reinterpret_cast<const float4*>(gp + 32);
        const float4 b1 = *reinterpret_cast<const float4*>(gp + 36);
        uint32_t* dst = s_p1 + c * 992 + pr * 32 + 8 * q;
        dst[0] = (uint32_t)(__float2int_rn(a0.x * SCALE) | (__float2int_rn(b0.x * SCALE) << 16));
        dst[1] = (uint32_t)(__float2int_rn(a0.y * SCALE) | (__float2int_rn(b0.y * SCALE) << 16));
        dst[2] = (uint32_t)(__float2int_rn(a0.z * SCALE) | (__float2int_rn(b0.z * SCALE) << 16));
        dst[3] = (uint32_t)(__float2int_rn(a0.w * SCALE) | (__float2int_rn(b0.w * SCALE) << 16));
        dst[4] = (uint32_t)(__float2int_rn(a1.x * SCALE) | (__float2int_rn(b1.x * SCALE) << 16));
        dst[5] = (uint32_t)(__float2int_rn(a1.y * SCALE) | (__float2int_rn(b1.y * SCALE) << 16));
        dst[6] = (uint32_t)(__float2int_rn(a1.z * SCALE) | (__float2int_rn(b1.z * SCALE) << 16));
        dst[7] = (uint32_t)(__float2int_rn(a1.w * SCALE) | (__float2int_rn(b1.w * SCALE) << 16));
    }

    // ---- quantize+pack conv weights; zero P2 pad columns ----
    {
        // w1 [o][c][kh][kw] -> s_w1r[(c*5+kh)*48 + o*8 + kw]
        for (int i = tid; i < 450; i += NT) {
            const int o = i / 75, r = i - o * 75;      // r = c*25 + kh*5 + kw
            const int rk = r / 5, kw = r - rk * 5;     // rk = c*5 + kh
            const int v = __float2int_rn(g_w1[i] * SCALE);
            s_w1r[rk * 48 + o * 8 + kw] = (uint32_t)(v | (v << 16));
        }
        // w2 [o][c][kh][kw] -> s_w2p[o*240 + rk*8 + kw]
        for (int i = tid; i < 2400; i += NT) {
            const int o = i / 150, r = i - o * 150;
            const int rk = r / 5, kw = r - rk * 5;
            const int v = __float2int_rn(g_w2[i] * SCALE);
            s_w2p[o * 240 + rk * 8 + kw] = (uint32_t)(v | (v << 16));
        }
        // P2 padding cols 14,15 of each pair-row (read only by discarded chains)
        for (int i = tid; i < 78; i += NT) {
            s_p2[i * 16 + 14] = 0u;
            s_p2[i * 16 + 15] = 0u;
        }
    }
    __syncthreads();

    // ---- Layer 1: (3->6) conv5+relu+pool2, one output-PAIR per thread ----
    if (tid < 588) {                          // 14 rows * 6 ch * 7 pairs
        const int ph  = tid / 42;             // out row 0..13
        const int rem = tid - ph * 42;
        const int o   = rem / 7;              // out channel 0..5
        const int pwp = rem - o * 7;          // pair 0..6 -> cols 2pwp, 2pwp+1
        int m0, m1;
        mp_pair<3, 992, 32, 48>(s_p1 + (2 * ph) * 32 + 4 * pwp, s_w1r + o * 8, m0, m1);
        const uint16_t v0 = (uint16_t)max(m0 - IONE, 0);
        const uint16_t v1 = (uint16_t)max(m1 - IONE, 0);
        uint16_t* p2h = reinterpret_cast<uint16_t*>(s_p2);
        const int pw0 = 2 * pwp;
        // P2[o][i][col]: lo = L1 row i, hi = L1 row i+1  (i in 0..12, stride 16)
        if (ph <= 12) {
            p2h[2 * (o * 208 + ph * 16 + pw0)]           = v0;
            p2h[2 * (o * 208 + ph * 16 + pw0 + 1)]       = v1;
        }
        if (ph >= 1) {
            p2h[2 * (o * 208 + (ph - 1) * 16 + pw0) + 1]     = v0;
            p2h[2 * (o * 208 + (ph - 1) * 16 + pw0 + 1) + 1] = v1;
        }
    }
    __syncthreads();

    // ---- Layer 2: (6->16) conv5+relu+pool2, 2 threads per output-pair
    //      (3 input channels each), shfl-combined ----
    if (tid < 480) {                          // 16 o * 5 ph * 3 colgroups * 2
        const int half = tid & 1;
        const int pi   = tid >> 1;            // 0..239
        const int o    = pi / 15;
        const int rem  = pi - o * 15;
        const int ph   = rem / 3;             // out row 0..4
        const int cg   = rem - ph * 3;        // colgroup: pw = 2cg, 2cg+1 (cg2: pw 4 only)
        int m0, m1;
        mp_pair<3, 208, 16, 8>(s_p2 + (half * 3) * 208 + (2 * ph) * 16 + 4 * cg,
                               s_w2p + o * 240 + half * 120, m0, m1);
        m0 = max(m0, __shfl_xor_sync(0xffffffffu, m0, 1));
        m1 = max(m1, __shfl_xor_sync(0xffffffffu, m1, 1));
        if (half == 0) {
            const int base = o * 25 + ph * 5 + 2 * cg;
            s_l2f[base] = (float)max(m0 - IONE, 0) * ISCALE;
            if (cg < 2) s_l2f[base + 1] = (float)max(m1 - IONE, 0) * ISCALE;
        }
    }
    __syncthreads();

    // ---- Layer 3: (16->120), 4 threads per output, 25 LDG.128 in flight ----
    if (tid < 480) {
        const int o = tid >> 2;
        const int q = tid & 3;
        const float4* w4 = reinterpret_cast<const float4*>(g_w3 + (size_t)o * 400 + q * 100);
        const float4* x4 = reinterpret_cast<const float4*>(s_l2f) + q * 25;
        float m = 0.f;
        #pragma unroll
        for (int k = 0; k < 25; ++k) {
            const float4 wv = w4[k];
            const float4 xv = x4[k];
            m = fmaxf(m, xv.x + wv.x);
            m = fmaxf(m, xv.y + wv.y);
            m = fmaxf(m, xv.z + wv.z);
            m = fmaxf(m, xv.w + wv.w);
        }
        m = fmaxf(m, __shfl_xor_sync(0xffffffffu, m, 1));
        m = fmaxf(m, __shfl_xor_sync(0xffffffffu, m, 2));
        if (q == 0) s_l3[o] = fmaxf(0.f, m - 1.f);
    }
    asm volatile("cp.async.wait_group 0;\n");
    __syncthreads();

    // ---- DenseDefuzzy: h = tanh(l3 @ wd), 4 threads per output ----
    {
        const int q  = tid & 3;
        const int j  = tid >> 2;
        const int jj = (j < 84) ? j : 83;
        float acc = 0.f;
        const int k0 = q * 30;
        #pragma unroll
        for (int k = 0; k < 30; ++k)
            acc += s_l3[k0 + k] * s_wd[(k0 + k) * 84 + jj];
        acc += __shfl_xor_sync(0xffffffffu, acc, 1);
        acc += __shfl_xor_sync(0xffffffffu, acc, 2);
        if (q == 0 && j < 84) s_h[j] = tanhf(acc);
    }
    __syncthreads();

    // ---- fc5 + log_softmax in warp 0 ----
    if (warp == 0) {
        const int l = (lane < 10) ? lane : 9;
        float acc = s_bf[l];
        #pragma unroll
        for (int j = 0; j < 84; ++j)
            acc += s_h[j] * s_wf[j * 10 + l];
        float v = (lane < 10) ? acc : -1e30f;
        #pragma unroll
        for (int s = 16; s; s >>= 1)
            v = fmaxf(v, __shfl_xor_sync(0xffffffffu, v, s));
        float e = (lane < 10) ? expf(acc - v) : 0.f;
        #pragma unroll
        for (int s = 16; s; s >>= 1)
            e += __shfl_xor_sync(0xffffffffu, e, s);
        const float ls = v + logf(e);
        if (lane < 10) g_out[(size_t)b * 10 + lane] = acc - ls;
    }
}

extern "C" void kernel_launch(void* const* d_in, const int* in_sizes, int n_in,
                              void* d_out, int out_size)
{
    const float* inp = (const float*)d_in[0];
    const float* w1  = (const float*)d_in[1];
    const float* w2  = (const float*)d_in[2];
    const float* w3  = (const float*)d_in[3];
    const float* wd  = (const float*)d_in[4];
    const float* wf  = (const float*)d_in[5];
    const float* bf  = (const float*)d_in[6];
    float* out = (float*)d_out;

    const int B = in_sizes[0] / (3 * 32 * 32);
    const int smem_bytes = SMEM_WORDS * 4;
    cudaFuncSetAttribute(lenet_fuzzy_kernel,
                         cudaFuncAttributeMaxDynamicSharedMemorySize, smem_bytes);
    lenet_fuzzy_kernel<<<B, NT, smem_bytes>>>(inp, w1, w2, w3, wd, wf, bf, out);
}

// round 12
// speedup vs baseline: 1.1152x; 1.1004x over previous
#include <cuda_runtime.h>
#include <cstdint>

// Fuzzy LeNet-5, Yager p=1 == Lukasiewicz: conv_out = relu(max(x+w) - 1);
// relu/maxpool fold into one max over (2x2 pool)x(5x5 field).
// Convs in s16 fixed point (scale 16383) with DPX __viaddmax_s16x2 (1 instr =
// 2 max-plus terms). R12: mp_pair software-pipelined (double-buffered block
// loads so LDS latency hides under the DPX chain); 56/120 of w3 prefetched
// to smem via cp.async.cg during conv phases.

#define NT 640
#define SCALE 16383.0f
#define ISCALE (1.0f / 16383.0f)
#define IONE 16383

__device__ __forceinline__ unsigned smem_u32(const void* p) {
    return (unsigned)__cvta_generic_to_shared(p);
}
__device__ __forceinline__ void cp8(float* dst, const float* src) {
    asm volatile("cp.async.ca.shared.global [%0], [%1], 8;\n"
                 :: "r"(smem_u32(dst)), "l"(src));
}
__device__ __forceinline__ void cp16(float* dst, const float* src) {
    asm volatile("cp.async.cg.shared.global [%0], [%1], 16;\n"
                 :: "r"(smem_u32(dst)), "l"(src));
}

// Pooled max-plus pair of cells, software-pipelined: block k+1's X/W are
// loaded before block k's 20 DPX run. x: packed pair-rows at (2ph, 4pwp),
// 16B-aligned. w: weight base; block (c,kh) at w + (c*5+kh)*WSTRIDE.
template<int NC, int CSTRIDE, int PITCH, int WSTRIDE>
__device__ __forceinline__ void mp_pair(const uint32_t* __restrict__ x,
                                        const uint32_t* __restrict__ w,
                                        int& m0, int& m1)
{
    uint32_t A0 = 0u, A1 = 0u, B0 = 0u, B1 = 0u;
    uint4 Xa = *reinterpret_cast<const uint4*>(x);
    uint4 Xb = *reinterpret_cast<const uint4*>(x + 4);
    uint4 Wv = *reinterpret_cast<const uint4*>(w);
    uint32_t w4 = w[4];
    #pragma unroll
    for (int blk = 0; blk < NC * 5; ++blk) {
        // prefetch next block (clamped dead-load on the last iteration)
        const int nb  = (blk + 1 < NC * 5) ? blk + 1 : blk;
        const int nc  = nb / 5, nkh = nb - nc * 5;
        const uint32_t* xr = x + nc * CSTRIDE + nkh * PITCH;
        const uint32_t* wr = w + nb * WSTRIDE;
        const uint4 nXa = *reinterpret_cast<const uint4*>(xr);
        const uint4 nXb = *reinterpret_cast<const uint4*>(xr + 4);
        const uint4 nWv = *reinterpret_cast<const uint4*>(wr);
        const uint32_t nw4 = wr[4];
        // 20 DPX on current regs (4 independent chains)
        A0 = __viaddmax_s16x2(Xa.x, Wv.x, A0);
        A1 = __viaddmax_s16x2(Xa.y, Wv.x, A1);
        B0 = __viaddmax_s16x2(Xa.z, Wv.x, B0);
        B1 = __viaddmax_s16x2(Xa.w, Wv.x, B1);
        A0 = __viaddmax_s16x2(Xa.y, Wv.y, A0);
        A1 = __viaddmax_s16x2(Xa.z, Wv.y, A1);
        B0 = __viaddmax_s16x2(Xa.w, Wv.y, B0);
        B1 = __viaddmax_s16x2(Xb.x, Wv.y, B1);
        A0 = __viaddmax_s16x2(Xa.z, Wv.z, A0);
        A1 = __viaddmax_s16x2(Xa.w, Wv.z, A1);
        B0 = __viaddmax_s16x2(Xb.x, Wv.z, B0);
        B1 = __viaddmax_s16x2(Xb.y, Wv.z, B1);
        A0 = __viaddmax_s16x2(Xa.w, Wv.w, A0);
        A1 = __viaddmax_s16x2(Xb.x, Wv.w, A1);
        B0 = __viaddmax_s16x2(Xb.y, Wv.w, B0);
        B1 = __viaddmax_s16x2(Xb.z, Wv.w, B1);
        A0 = __viaddmax_s16x2(Xb.x, w4, A0);
        A1 = __viaddmax_s16x2(Xb.y, w4, A1);
        B0 = __viaddmax_s16x2(Xb.z, w4, B0);
        B1 = __viaddmax_s16x2(Xb.w, w4, B1);
        Xa = nXa; Xb = nXb; Wv = nWv; w4 = nw4;
    }
    const uint32_t ca = __viaddmax_s16x2(A0, 0u, A1);
    const uint32_t cb = __viaddmax_s16x2(B0, 0u, B1);
    m0 = max((int)(ca & 0xFFFFu), (int)(ca >> 16));   // values <= 32766
    m1 = max((int)(cb & 0xFFFFu), (int)(cb >> 16));
}

// dynamic smem layout (32-bit words)
#define OFF_W1R  0       // 720 u32: [c*5+kh][o:6][8] padded (w,w)
#define OFF_P1   736     // 2976 u32: [3][31][32] input pair-rows (128B rows)
#define OFF_P2   3712    // 1248 u32: [6][13][16] L1-out pair-rows (padded)
#define OFF_W2P  4960    // 3840 u32: [16][6][5][8]
#define OFF_L2F  8800    // 400 f (16B aligned)
#define OFF_L3   9200    // 120 f
#define OFF_H    9320    // 84 f
#define OFF_WD   9404    // 10080 f (8B aligned)
#define OFF_WF   19484   // 840 f
#define OFF_BF   20324   // 10 f
#define OFF_W3S  20336   // 22400 f: w3 outputs 0..55 (16B aligned)
#define SMEM_WORDS 42736

__global__ __launch_bounds__(NT, 1)
void lenet_fuzzy_kernel(const float* __restrict__ g_in,
                        const float* __restrict__ g_w1,
                        const float* __restrict__ g_w2,
                        const float* __restrict__ g_w3,
                        const float* __restrict__ g_wd,
                        const float* __restrict__ g_wf,
                        const float* __restrict__ g_bf,
                        float* __restrict__ g_out)
{
    extern __shared__ uint32_t sm[];
    uint32_t* s_w1r = sm + OFF_W1R;
    uint32_t* s_p1  = sm + OFF_P1;
    uint32_t* s_p2  = sm + OFF_P2;
    uint32_t* s_w2p = sm + OFF_W2P;
    float*    s_l2f = reinterpret_cast<float*>(sm + OFF_L2F);
    float*    s_l3  = reinterpret_cast<float*>(sm + OFF_L3);
    float*    s_h   = reinterpret_cast<float*>(sm + OFF_H);
    float*    s_wd  = reinterpret_cast<float*>(sm + OFF_WD);
    float*    s_wf  = reinterpret_cast<float*>(sm + OFF_WF);
    float*    s_bf  = reinterpret_cast<float*>(sm + OFF_BF);
    float*    s_w3f = reinterpret_cast<float*>(sm + OFF_W3S);

    const int b    = blockIdx.x;
    const int tid  = threadIdx.x;
    const int warp = tid >> 5;
    const int lane = tid & 31;

    // ---- group 0: w3 outputs 0..55 -> smem (consumed at L3) ----
    for (int i = tid; i < 5600; i += NT) cp16(s_w3f + 4 * i, g_w3 + 4 * i);
    asm volatile("cp.async.commit_group;\n");
    // ---- group 1: head weights (consumed after L3) ----
    for (int i = tid; i < 5040; i += NT) cp8(s_wd + 2 * i, g_wd + 2 * i);
    for (int i = tid; i < 420;  i += NT) cp8(s_wf + 2 * i, g_wf + 2 * i);
    if (tid < 5) cp8(s_bf + 2 * tid, g_bf + 2 * tid);
    asm volatile("cp.async.commit_group;\n");

    // ---- quantize input DIRECTLY from global into pair-rows
    //      P1[c][i][col] = (row i, row i+1); job = (c, pair-row i, 8-col group)
    if (tid < 372) {                          // 3 ch * 31 rows * 4 groups
        const int c   = tid / 124;
        const int rem = tid - c * 124;
        const int pr  = rem >> 2;             // pair row 0..30
        const int q   = rem & 3;              // col group: cols 8q..8q+7
        const float* gp = g_in + (size_t)b * 3072 + c * 1024 + pr * 32 + 8 * q;
        const float4 a0 = *reinterpret_cast<const float4*>(gp);
        const float4 a1 = *reinterpret_cast<const float4*>(gp + 4);
        const float4 b0 = *reinterpret_cast<const float4*>(gp + 32);
        const float4 b1 = *reinterpret_cast<const float4*>(gp + 36);
        uint32_t* dst = s_p1 + c * 992 + pr * 32 + 8 * q;
        dst[0] = (uint32_t)(__float2int_rn(a0.x * SCALE) | (__float2int_rn(b0.x * SCALE) << 16));
        dst[1] = (uint32_t)(__float2int_rn(a0.y * SCALE) | (__float2int_rn(b0.y * SCALE) << 16));
        dst[2] = (uint32_t)(__float2int_rn(a0.z * SCALE) | (__float2int_rn(b0.z * SCALE) << 16));
        dst[3] = (uint32_t)(__float2int_rn(a0.w * SCALE) | (__float2int_rn(b0.w * SCALE) << 16));
        dst[4] = (uint32_t)(__float2int_rn(a1.x * SCALE) | (__float2int_rn(b1.x * SCALE) << 16));
        dst[5] = (uint32_t)(__float2int_rn(a1.y * SCALE) | (__float2int_rn(b1.y * SCALE) << 16));
        dst[6] = (uint32_t)(__float2int_rn(a1.z * SCALE) | (__float2int_rn(b1.z * SCALE) << 16));
        dst[7] = (uint32_t)(__float2int_rn(a1.w * SCALE) | (__float2int_rn(b1.w * SCALE) << 16));
    }

    // ---- quantize+pack conv weights; zero P2 pad columns ----
    {
        // w1 [o][c][kh][kw] -> s_w1r[(c*5+kh)*48 + o*8 + kw]
        for (int i = tid; i < 450; i += NT) {
            const int o = i / 75, r = i - o * 75;      // r = c*25 + kh*5 + kw
            const int rk = r / 5, kw = r - rk * 5;     // rk = c*5 + kh
            const int v = __float2int_rn(g_w1[i] * SCALE);
            s_w1r[rk * 48 + o * 8 + kw] = (uint32_t)(v | (v << 16));
        }
        // w2 [o][c][kh][kw] -> s_w2p[o*240 + rk*8 + kw]
        for (int i = tid; i < 2400; i += NT) {
            const int o = i / 150, r = i - o * 150;
            const int rk = r / 5, kw = r - rk * 5;
            const int v = __float2int_rn(g_w2[i] * SCALE);
            s_w2p[o * 240 + rk * 8 + kw] = (uint32_t)(v | (v << 16));
        }
        // P2 padding cols 14,15 of each pair-row (read only by discarded chains)
        for (int i = tid; i < 78; i += NT) {
            s_p2[i * 16 + 14] = 0u;
            s_p2[i * 16 + 15] = 0u;
        }
    }
    __syncthreads();

    // ---- Layer 1: (3->6) conv5+relu+pool2, one output-PAIR per thread ----
    if (tid < 588) {                          // 14 rows * 6 ch * 7 pairs
        const int ph  = tid / 42;             // out row 0..13
        const int rem = tid - ph * 42;
        const int o   = rem / 7;              // out channel 0..5
        const int pwp = rem - o * 7;          // pair 0..6 -> cols 2pwp, 2pwp+1
        int m0, m1;
        mp_pair<3, 992, 32, 48>(s_p1 + (2 * ph) * 32 + 4 * pwp, s_w1r + o * 8, m0, m1);
        const uint16_t v0 = (uint16_t)max(m0 - IONE, 0);
        const uint16_t v1 = (uint16_t)max(m1 - IONE, 0);
        uint16_t* p2h = reinterpret_cast<uint16_t*>(s_p2);
        const int pw0 = 2 * pwp;
        // P2[o][i][col]: lo = L1 row i, hi = L1 row i+1  (i in 0..12, stride 16)
        if (ph <= 12) {
            p2h[2 * (o * 208 + ph * 16 + pw0)]           = v0;
            p2h[2 * (o * 208 + ph * 16 + pw0 + 1)]       = v1;
        }
        if (ph >= 1) {
            p2h[2 * (o * 208 + (ph - 1) * 16 + pw0) + 1]     = v0;
            p2h[2 * (o * 208 + (ph - 1) * 16 + pw0 + 1) + 1] = v1;
        }
    }
    __syncthreads();

    // ---- Layer 2: (6->16) conv5+relu+pool2, 2 threads per output-pair
    //      (3 input channels each), shfl-combined ----
    if (tid < 480) {                          // 16 o * 5 ph * 3 colgroups * 2
        const int half = tid & 1;
        const int pi   = tid >> 1;            // 0..239
        const int o    = pi / 15;
        const int rem  = pi - o * 15;
        const int ph   = rem / 3;             // out row 0..4
        const int cg   = rem - ph * 3;        // colgroup: pw = 2cg, 2cg+1 (cg2: pw 4 only)
        int m0, m1;
        mp_pair<3, 208, 16, 8>(s_p2 + (half * 3) * 208 + (2 * ph) * 16 + 4 * cg,
                               s_w2p + o * 240 + half * 120, m0, m1);
        m0 = max(m0, __shfl_xor_sync(0xffffffffu, m0, 1));
        m1 = max(m1, __shfl_xor_sync(0xffffffffu, m1, 1));
        if (half == 0) {
            const int base = o * 25 + ph * 5 + 2 * cg;
            s_l2f[base] = (float)max(m0 - IONE, 0) * ISCALE;
            if (cg < 2) s_l2f[base + 1] = (float)max(m1 - IONE, 0) * ISCALE;
        }
    }
    asm volatile("cp.async.wait_group 1;\n");   // w3[0..55] staged
    __syncthreads();

    // ---- Layer 3: (16->120), 4 threads per output.
    //      Outputs 0..55 from smem (warps 0-6), 56..119 from global (7-14) ----
    if (tid < 480) {
        const int o = tid >> 2;
        const int q = tid & 3;
        const float4* x4 = reinterpret_cast<const float4*>(s_l2f) + q * 25;
        float m = 0.f;
        if (o < 56) {
            const float4* w4 = reinterpret_cast<const float4*>(s_w3f) + o * 100 + q * 25;
            #pragma unroll
            for (int k = 0; k < 25; ++k) {
                const float4 wv = w4[k];
                const float4 xv = x4[k];
                m = fmaxf(m, xv.x + wv.x);
                m = fmaxf(m, xv.y + wv.y);
                m = fmaxf(m, xv.z + wv.z);
                m = fmaxf(m, xv.w + wv.w);
            }
        } else {
            const float4* w4 = reinterpret_cast<const float4*>(g_w3) + o * 100 + q * 25;
            #pragma unroll
            for (int k = 0; k < 25; ++k) {
                const float4 wv = w4[k];
                const float4 xv = x4[k];
                m = fmaxf(m, xv.x + wv.x);
                m = fmaxf(m, xv.y + wv.y);
                m = fmaxf(m, xv.z + wv.z);
                m = fmaxf(m, xv.w + wv.w);
            }
        }
        m = fmaxf(m, __shfl_xor_sync(0xffffffffu, m, 1));
        m = fmaxf(m, __shfl_xor_sync(0xffffffffu, m, 2));
        if (q == 0) s_l3[o] = fmaxf(0.f, m - 1.f);
    }
    asm volatile("cp.async.wait_group 0;\n");
    __syncthreads();

    // ---- DenseDefuzzy: h = tanh(l3 @ wd), 4 threads per output ----
    {
        const int q  = tid & 3;
        const int j  = tid >> 2;
        const int jj = (j < 84) ? j : 83;
        float acc = 0.f;
        const int k0 = q * 30;
        #pragma unroll
        for (int k = 0; k < 30; ++k)
            acc += s_l3[k0 + k] * s_wd[(k0 + k) * 84 + jj];
        acc += __shfl_xor_sync(0xffffffffu, acc, 1);
        acc += __shfl_xor_sync(0xffffffffu, acc, 2);
        if (q == 0 && j < 84) s_h[j] = tanhf(acc);
    }
    __syncthreads();

    // ---- fc5 + log_softmax in warp 0 ----
    if (warp == 0) {
        const int l = (lane < 10) ? lane : 9;
        float acc = s_bf[l];
        #pragma unroll
        for (int j = 0; j < 84; ++j)
            acc += s_h[j] * s_wf[j * 10 + l];
        float v = (lane < 10) ? acc : -1e30f;
        #pragma unroll
        for (int s = 16; s; s >>= 1)
            v = fmaxf(v, __shfl_xor_sync(0xffffffffu, v, s));
        float e = (lane < 10) ? expf(acc - v) : 0.f;
        #pragma unroll
        for (int s = 16; s; s >>= 1)
            e += __shfl_xor_sync(0xffffffffu, e, s);
        const float ls = v + logf(e);
        if (lane < 10) g_out[(size_t)b * 10 + lane] = acc - ls;
    }
}

extern "C" void kernel_launch(void* const* d_in, const int* in_sizes, int n_in,
                              void* d_out, int out_size)
{
    const float* inp = (const float*)d_in[0];
    const float* w1  = (const float*)d_in[1];
    const float* w2  = (const float*)d_in[2];
    const float* w3  = (const float*)d_in[3];
    const float* wd  = (const float*)d_in[4];
    const float* wf  = (const float*)d_in[5];
    const float* bf  = (const float*)d_in[6];
    float* out = (float*)d_out;

    const int B = in_sizes[0] / (3 * 32 * 32);
    const int smem_bytes = SMEM_WORDS * 4;
    cudaFuncSetAttribute(lenet_fuzzy_kernel,
                         cudaFuncAttributeMaxDynamicSharedMemorySize, smem_bytes);
    lenet_fuzzy_kernel<<<B, NT, smem_bytes>>>(inp, w1, w2, w3, wd, wf, bf, out);
}